// round 12
// baseline (speedup 1.0000x reference)
#include <cuda_runtime.h>
#include <cuda_fp16.h>

// Shapes
#define BB   2
#define HH   160
#define WW   160
#define DD   96
#define WOUT 154
#define CHST (160*160*96)          // x channel stride (elements)
#define Y_ELEMS (BB*HH*WW*DD)      // 4,915,200

// Fused tiling: blocks tile (w-chunk x h-seg x (b, d-half)); all exact
#define WOCF 7                     // w outputs per block (154 = 22*7)
#define WICF 13
#define SEGH 22                    // h outputs per block (154 = 7*22)
#define NHSEG 7
#define NWCH 22
#define TPB  384
#define TOTB (NWCH*NHSEG*BB*2)     // 616
#define PQ   315                   // positions per block = 7*45
#define DIN  52                    // input d per half
#define DLN  46                    // D-window line outputs per half
#define NITER (SEGH+6)             // 28
#define NA   (WICF*DIN)            // 676 stage-A items
#define NF   676                   // per-field SoA stride

// smem byte offsets (total 69,600 B -> 3 CTAs/SM)
#define OFF_F    0                  // u32[5*676] SoA: A01,A23,B01,B23,N
#define OFF_LSAB 13520              // uint4[13*46] D-window line sums (AoS)
#define OFF_LSN  23088              // u32 [13*46]
#define OFF_RAB  25488              // uint4[7*315] ring of W-window sums
#define OFF_RN   60768              // u32 [7*315]
#define SMEMF    69600

__device__ double   g_acc;          // zero-init at load; reset by last block
__device__ unsigned g_done;

__device__ __forceinline__ __half2 u2h(unsigned u) { return *reinterpret_cast<__half2*>(&u); }
__device__ __forceinline__ unsigned h2u(__half2 h) { return *reinterpret_cast<unsigned*>(&h); }

__device__ __forceinline__ void nd_class(float A, float B, float Nf,
                                         float& num, float& den)
{
    const float inv343 = 1.0f / 343.0f;
    const float K2C = 49.0f / 48.0f;
    const float K4C = K2C * K2C;
    const float Cc  = 0.00045f;            // (0.03*1)^2/2
    float yb  = Nf * inv343;
    float g1  = 1.0f - yb;
    float Ab  = A * inv343;
    float Bb  = B * inv343;
    num = fmaf(K2C * Ab, g1, Cc);
    float var = fmaf(-Ab, Ab, Bb);
    den = fmaf((K4C * var) * yb, g1, Cc);
}

__global__ __launch_bounds__(TPB, 3) void kf(const float* __restrict__ X,
                                             const int* __restrict__ Y,
                                             float* __restrict__ out)
{
    extern __shared__ char sm[];
    unsigned* fld  = (unsigned*)(sm + OFF_F);     // 5 SoA fields, stride NF
    unsigned* lsW  = (unsigned*)(sm + OFF_LSAB);  // uint4 viewed as u32
    uint4*    lsAB = (uint4*)(sm + OFF_LSAB);
    unsigned* lsN  = (unsigned*)(sm + OFF_LSN);
    uint4*    rAB  = (uint4*)(sm + OFF_RAB);
    unsigned* rN   = (unsigned*)(sm + OFF_RN);

    const int tid = threadIdx.x;
    const int wb  = blockIdx.x * WOCF;
    const int h0  = blockIdx.y * SEGH;
    const int b   = blockIdx.z >> 1;
    const int gHalf = blockIdx.z & 1;      // d-half: 0 -> outputs 0..44, 1 -> 45..89
    const int d0  = gHalf * 44;            // input d base (52 inputs)

    // ---- y dtype probe (int64 -> odd 32-bit words all zero) ----
    __shared__ int s_ys;
    if (tid == 0) s_ys = 2;
    __syncthreads();
    if (tid < 128) { if (Y[2 * tid + 1] != 0) s_ys = 1; }
    __syncthreads();
    const int ys = s_ys;

    const float* Xb = X + (size_t)b * 4 * CHST;
    const int*   Yb = Y + (size_t)ys * (size_t)b * (HH * WW * DD);

    // stage-A ownership (2 items max per thread)
    int off0 = 0, off1 = 0;
    const bool hasA1 = (tid + TPB < NA);
    { int wl = tid / DIN, dl = tid - wl * DIN; off0 = (wb + wl) * 96 + d0 + dl; }
    if (hasA1) { int i1 = tid + TPB; int wl = i1 / DIN, dl = i1 - wl * DIN; off1 = (wb + wl) * 96 + d0 + dl; }

    // stage-B ownership: 130 items = field(5) x line(13) x chunk(2), field-major
    const bool hasB = (tid < 130);
    int bf = 0; const unsigned* bsrc = fld; unsigned* bdst = lsW; int bstride = 4;
    if (hasB) {
        bf = tid / 26;
        int rem = tid - bf * 26;
        int line = rem >> 1;
        int chunk = rem & 1;
        bsrc = fld + bf * NF + line * DIN + chunk * 23;
        if (bf < 4) { bdst = lsW + (line * DLN + chunk * 23) * 4 + bf; bstride = 4; }
        else        { bdst = lsN + line * DLN + chunk * 23;           bstride = 1; }
    }

    // stage-C ownership: sliding-H accumulators, one position per thread
    float4 aA = make_float4(0.f, 0.f, 0.f, 0.f);
    float4 aB = aA;
    unsigned s02 = 0u, s13 = 0u;
    float lsum = 0.f;
    const int pw = (tid < PQ) ? (tid / 45) : 0;
    const int pd = (tid < PQ) ? (tid - pw * 45) : 0;
    const int lidx = pd + gHalf;

    // ---- prefetch row 0: y then x[y] only ----
    int   pk0 = 0, pk1 = 0;
    float pv0 = 0.f, pv1 = 0.f;
    {
        const float* Xl = Xb + (size_t)h0 * (WW * DD);
        const int*   Yl = Yb + (size_t)ys * (size_t)h0 * (WW * DD);
        pk0 = Yl[off0 * ys]; pv0 = Xl[off0 + pk0 * CHST];
        if (hasA1) { pk1 = Yl[off1 * ys]; pv1 = Xl[off1 + pk1 * CHST]; }
    }

    for (int hh = 0; hh < NITER; ++hh) {
        // ---- Stage A: a = 0.5*tanh(0.5*x[y]); SoA expanded store ----
        {
            float th;
            asm("tanh.approx.f32 %0, %1;" : "=f"(th) : "f"(0.5f * pv0));
            float a = 0.5f * th;
            unsigned ha = (unsigned)__half_as_ushort(__float2half_rn(a));
            unsigned hb = (unsigned)__half_as_ushort(__float2half_rn(a * a));
            int sh = (pk0 & 1) ? 16 : 0;
            unsigned sa = ha << sh, sbv = hb << sh;
            bool hi = (pk0 & 2) != 0;
            fld[tid]          = hi ? 0u : sa;
            fld[NF + tid]     = hi ? sa : 0u;
            fld[2*NF + tid]   = hi ? 0u : sbv;
            fld[3*NF + tid]   = hi ? sbv : 0u;
            fld[4*NF + tid]   = 1u << (pk0 * 8);
        }
        if (hasA1) {
            float th;
            asm("tanh.approx.f32 %0, %1;" : "=f"(th) : "f"(0.5f * pv1));
            float a = 0.5f * th;
            unsigned ha = (unsigned)__half_as_ushort(__float2half_rn(a));
            unsigned hb = (unsigned)__half_as_ushort(__float2half_rn(a * a));
            int sh = (pk1 & 1) ? 16 : 0;
            unsigned sa = ha << sh, sbv = hb << sh;
            bool hi = (pk1 & 2) != 0;
            int i1 = tid + TPB;
            fld[i1]          = hi ? 0u : sa;
            fld[NF + i1]     = hi ? sa : 0u;
            fld[2*NF + i1]   = hi ? 0u : sbv;
            fld[3*NF + i1]   = hi ? sbv : 0u;
            fld[4*NF + i1]   = 1u << (pk1 * 8);
        }
        // ---- issue prefetch for next row (hidden behind stages B+C) ----
        if (hh + 1 < NITER) {
            const int hN = h0 + hh + 1;
            const float* Xl = Xb + (size_t)hN * (WW * DD);
            const int*   Yl = Yb + (size_t)ys * (size_t)hN * (WW * DD);
            pk0 = Yl[off0 * ys]; pv0 = Xl[off0 + pk0 * CHST];
            if (hasA1) { pk1 = Yl[off1 * ys]; pv1 = Xl[off1 + pk1 * CHST]; }
        }
        __syncthreads();

        // ---- Stage B: D-window-7 by register sliding (per field) ----
        if (hasB) {
            if (bf < 4) {
                __half2 s = u2h(0u);
                #pragma unroll
                for (int i = 0; i < 7; ++i) s = __hadd2(s, u2h(bsrc[i]));
                bdst[0] = h2u(s);
                #pragma unroll
                for (int i = 1; i < 23; ++i) {
                    s = __hadd2(s, u2h(bsrc[i + 6]));
                    s = __hsub2(s, u2h(bsrc[i - 1]));
                    bdst[i * 4] = h2u(s);
                }
            } else {
                unsigned s = 0u;
                #pragma unroll
                for (int i = 0; i < 7; ++i) s += bsrc[i];
                bdst[0] = s;
                #pragma unroll
                for (int i = 1; i < 23; ++i) {
                    s += bsrc[i + 6] - bsrc[i - 1];
                    bdst[i] = s;
                }
            }
        }
        __syncthreads();

        // ---- Stage C: W-window-7 + sliding-H update + finalize ----
        if (tid < PQ) {
            const __half2 hz = u2h(0u);
            __half2 A01 = hz, A23 = hz, B01 = hz, B23 = hz;
            unsigned n = 0u;
            #pragma unroll
            for (int j7 = 0; j7 < 7; ++j7) {
                int q = (pw + j7) * DLN + lidx;
                uint4 u = lsAB[q];
                A01 = __hadd2(A01, u2h(u.x)); A23 = __hadd2(A23, u2h(u.y));
                B01 = __hadd2(B01, u2h(u.z)); B23 = __hadd2(B23, u2h(u.w));
                n += lsN[q];
            }
            float2 fa01 = __half22float2(A01), fa23 = __half22float2(A23);
            float2 fb01 = __half22float2(B01), fb23 = __half22float2(B23);

            aA.x += fa01.x; aA.y += fa01.y; aA.z += fa23.x; aA.w += fa23.y;
            aB.x += fb01.x; aB.y += fb01.y; aB.z += fb23.x; aB.w += fb23.y;
            s02 += n & 0x00FF00FFu;
            s13 += (n >> 8) & 0x00FF00FFu;

            int rp = (hh % 7) * PQ + tid;
            if (hh >= 7) {
                uint4 oldv = rAB[rp];
                unsigned on = rN[rp];
                float2 c01 = __half22float2(u2h(oldv.x)), c23 = __half22float2(u2h(oldv.y));
                float2 d01 = __half22float2(u2h(oldv.z)), d23 = __half22float2(u2h(oldv.w));
                aA.x -= c01.x; aA.y -= c01.y; aA.z -= c23.x; aA.w -= c23.y;
                aB.x -= d01.x; aB.y -= d01.y; aB.z -= d23.x; aB.w -= d23.y;
                s02 -= on & 0x00FF00FFu;
                s13 -= (on >> 8) & 0x00FF00FFu;
            }
            rAB[rp] = make_uint4(h2u(A01), h2u(A23), h2u(B01), h2u(B23));
            rN[rp] = n;

            if (hh >= 6) {
                float N0 = (float)(s02 & 0xFFFFu);
                float N2 = (float)(s02 >> 16);
                float N1 = (float)(s13 & 0xFFFFu);
                float N3 = (float)(s13 >> 16);
                float n0, d0c, n1, d1, n2, d2, n3, d3;
                nd_class(aA.x, aB.x, N0, n0, d0c);
                nd_class(aA.y, aB.y, N1, n1, d1);
                nd_class(aA.z, aB.z, N2, n2, d2);
                nd_class(aA.w, aB.w, N3, n3, d3);
                float p01 = d0c * d1, p23 = d2 * d3;
                float num = fmaf(n0, d1, n1 * d0c) * p23 + fmaf(n2, d3, n3 * d2) * p01;
                lsum += __fdividef(num, p01 * p23);
            }
        }
        __syncthreads();
    }

    // ---- block reduce + global accumulate + last-block finalize ----
    float* red = (float*)sm;
    red[tid] = lsum;
    __syncthreads();
    if (tid < 128) red[tid] += red[tid + 128] + red[tid + 256];
    __syncthreads();
    if (tid < 64) red[tid] += red[tid + 64];
    __syncthreads();
    if (tid < 32) {
        float v = red[tid] + red[tid + 32];
        #pragma unroll
        for (int o = 16; o > 0; o >>= 1)
            v += __shfl_down_sync(0xffffffffu, v, o);
        if (tid == 0) {
            atomicAdd(&g_acc, (double)v);
            __threadfence();
            unsigned t = atomicAdd(&g_done, 1u);
            if (t == TOTB - 1) {
                double tot = g_acc;
                out[0] = (float)(1.0 - tot * (1.0 / 17075520.0));
                __threadfence();
                g_acc = 0.0;
                g_done = 0u;
            }
        }
    }
}

extern "C" void kernel_launch(void* const* d_in, const int* in_sizes, int n_in,
                              void* d_out, int out_size)
{
    (void)out_size;
    const float* X;
    const int*   Y;
    if (n_in >= 2 && in_sizes[0] == Y_ELEMS) {
        Y = (const int*)d_in[0];
        X = (const float*)d_in[1];
    } else {
        X = (const float*)d_in[0];
        Y = (const int*)d_in[1];
    }

    static int smem_set = 0;
    if (!smem_set) {
        cudaFuncSetAttribute(kf, cudaFuncAttributeMaxDynamicSharedMemorySize, SMEMF);
        smem_set = 1;
    }

    kf<<<dim3(NWCH, NHSEG, BB * 2), TPB, SMEMF>>>(X, Y, (float*)d_out);
}

// round 15
// speedup vs baseline: 1.0245x; 1.0245x over previous
#include <cuda_runtime.h>
#include <cuda_fp16.h>

// Shapes
#define BB   2
#define HH   160
#define WW   160
#define DD   96
#define WOUT 154
#define CHST (160*160*96)          // x channel stride (elements)
#define Y_ELEMS (BB*HH*WW*DD)      // 4,915,200

// Fused tiling: blocks tile (w-chunk x h-seg x (b, d-half)); all exact
#define WOCF 7                     // w outputs per block (154 = 22*7)
#define WICF 13
#define SEGH 22                    // h outputs per block (154 = 7*22)
#define NHSEG 7
#define NWCH 22
#define TPB  384
#define TOTB (NWCH*NHSEG*BB*2)     // 616
#define PQ   315                   // positions per block = 7*45
#define DIN  52                    // input d per half
#define DLN  46                    // D-window line outputs per half
#define NITER (SEGH+6)             // 28
#define NA   (WICF*DIN)            // 676 stage-A items
#define NB   (WICF*23)             // 299 stage-B pairs

// smem byte offsets (total 69,588 B -> 3 CTAs/SM); ALL uint4 offsets 16-aligned
#define OFF_EAB  0                  // uint4[676]  {A01,A23,B01,B23}        (0 % 16 == 0)
#define OFF_EN   10816              // u32 [676]   pre-shifted class count
#define OFF_LSAB 13520              // uint4[13*46] D-window line sums      (13520 % 16 == 0)
#define OFF_LSN  23088              // u32 [13*46]
#define OFF_RAB  25488              // uint4[7*315] ring of W-window sums   (25488 % 16 == 0)
#define OFF_RN   60768              // u32 [7*315]
#define SMEMF    69600

__device__ double   g_acc;          // zero-init at load; reset by last block
__device__ unsigned g_done;

__device__ __forceinline__ __half2 u2h(unsigned u) { return *reinterpret_cast<__half2*>(&u); }
__device__ __forceinline__ unsigned h2u(__half2 h) { return *reinterpret_cast<unsigned*>(&h); }

__device__ __forceinline__ void nd_class(float A, float B, float Nf,
                                         float& num, float& den)
{
    const float inv343 = 1.0f / 343.0f;
    const float K2C = 49.0f / 48.0f;
    const float K4C = K2C * K2C;
    const float Cc  = 0.00045f;            // (0.03*1)^2/2
    float yb  = Nf * inv343;
    float g1  = 1.0f - yb;
    float Ab  = A * inv343;
    float Bb  = B * inv343;
    num = fmaf(K2C * Ab, g1, Cc);
    float var = fmaf(-Ab, Ab, Bb);
    den = fmaf((K4C * var) * yb, g1, Cc);
}

// stage-A: convert one prefetched voxel and store expanded AoS entry
__device__ __forceinline__ void stageA_store(uint4* eab, unsigned* en,
                                             int idx, int k, float xv)
{
    float th;
    asm("tanh.approx.f32 %0, %1;" : "=f"(th) : "f"(0.5f * xv));
    float a = 0.5f * th;                   // sigmoid(x) - 0.5
    unsigned ha = (unsigned)__half_as_ushort(__float2half_rn(a));
    unsigned hb = (unsigned)__half_as_ushort(__float2half_rn(a * a));
    int sh = (k & 1) ? 16 : 0;
    unsigned sa = ha << sh, sbv = hb << sh;
    bool hi = (k & 2) != 0;
    eab[idx] = make_uint4(hi ? 0u : sa,  hi ? sa  : 0u,
                          hi ? 0u : sbv, hi ? sbv : 0u);
    en[idx] = 1u << (k * 8);
}

__global__ __launch_bounds__(TPB, 3) void kf(const float* __restrict__ X,
                                             const int* __restrict__ Y,
                                             float* __restrict__ out)
{
    extern __shared__ char sm[];
    uint4*    eab  = (uint4*)(sm + OFF_EAB);
    unsigned* en   = (unsigned*)(sm + OFF_EN);
    uint4*    lsAB = (uint4*)(sm + OFF_LSAB);
    unsigned* lsN  = (unsigned*)(sm + OFF_LSN);
    uint4*    rAB  = (uint4*)(sm + OFF_RAB);
    unsigned* rN   = (unsigned*)(sm + OFF_RN);

    const int tid = threadIdx.x;
    const int wb  = blockIdx.x * WOCF;
    const int h0  = blockIdx.y * SEGH;
    const int b   = blockIdx.z >> 1;
    const int gHalf = blockIdx.z & 1;      // d-half: 0 -> outputs 0..44, 1 -> 45..89
    const int d0  = gHalf * 44;            // input d base (52 inputs)

    // ---- y dtype probe (int64 -> odd 32-bit words all zero) ----
    __shared__ int s_ys;
    if (tid == 0) s_ys = 2;
    __syncthreads();
    if (tid < 128) { if (Y[2 * tid + 1] != 0) s_ys = 1; }
    __syncthreads();
    const int ys = s_ys;

    const float* Xb = X + (size_t)b * 4 * CHST;
    const int*   Yb = Y + (size_t)ys * (size_t)b * (HH * WW * DD);

    // stage-A ownership (items tid and tid+TPB)
    int off0, off1 = 0;
    const bool hasA1 = (tid + TPB < NA);   // tid < 292
    { int wl = tid / DIN, dl = tid - wl * DIN; off0 = (wb + wl) * 96 + d0 + dl; }
    if (hasA1) { int i1 = tid + TPB; int wl = i1 / DIN, dl = i1 - wl * DIN; off1 = (wb + wl) * 96 + d0 + dl; }

    // stage-C ownership: sliding-H accumulators, one position per thread
    float4 aA = make_float4(0.f, 0.f, 0.f, 0.f);
    float4 aB = aA;
    unsigned s02 = 0u, s13 = 0u;
    float lsum = 0.f;
    const int pw = (tid < PQ) ? (tid / 45) : 0;
    const int pd = (tid < PQ) ? (tid - pw * 45) : 0;
    const int lidx = pd + gHalf;

    // ---- prologue: prefetch + store row 0, prefetch row 1 ----
    int   pk0 = 0, pk1 = 0;
    float pv0 = 0.f, pv1 = 0.f;
    {
        const float* Xl = Xb + (size_t)h0 * (WW * DD);
        const int*   Yl = Yb + (size_t)ys * (size_t)h0 * (WW * DD);
        int k0 = Yl[off0 * ys]; float v0 = Xl[off0 + k0 * CHST];
        stageA_store(eab, en, tid, k0, v0);
        if (hasA1) { int k1 = Yl[off1 * ys]; float v1 = Xl[off1 + k1 * CHST];
                     stageA_store(eab, en, tid + TPB, k1, v1); }
    }
    {
        const float* Xl = Xb + (size_t)(h0 + 1) * (WW * DD);
        const int*   Yl = Yb + (size_t)ys * (size_t)(h0 + 1) * (WW * DD);
        pk0 = Yl[off0 * ys]; pv0 = Xl[off0 + pk0 * CHST];
        if (hasA1) { pk1 = Yl[off1 * ys]; pv1 = Xl[off1 + pk1 * CHST]; }
    }

    const __half2 hz = u2h(0u);

    for (int hh = 0; hh < NITER; ++hh) {
        __syncthreads();                     // eab(hh) ready for B

        // ---- Stage B: D-window-7, paired (2 outputs share 6-tap core) ----
        if (tid < NB) {
            int wl = tid / 23;
            int de = (tid - wl * 23) * 2;
            int base = wl * DIN + de;
            __half2 A01 = hz, A23 = hz, B01 = hz, B23 = hz;
            unsigned n = 0u;
            #pragma unroll
            for (int t7 = 1; t7 < 7; ++t7) {
                uint4 u = eab[base + t7];
                A01 = __hadd2(A01, u2h(u.x)); A23 = __hadd2(A23, u2h(u.y));
                B01 = __hadd2(B01, u2h(u.z)); B23 = __hadd2(B23, u2h(u.w));
                n += en[base + t7];
            }
            uint4 u0v = eab[base];
            uint4 u7v = eab[base + 7];
            unsigned n0 = en[base], n7 = en[base + 7];
            int o = wl * DLN + de;
            lsAB[o]   = make_uint4(h2u(__hadd2(A01, u2h(u0v.x))), h2u(__hadd2(A23, u2h(u0v.y))),
                                   h2u(__hadd2(B01, u2h(u0v.z))), h2u(__hadd2(B23, u2h(u0v.w))));
            lsN[o]    = n + n0;
            lsAB[o+1] = make_uint4(h2u(__hadd2(A01, u2h(u7v.x))), h2u(__hadd2(A23, u2h(u7v.y))),
                                   h2u(__hadd2(B01, u2h(u7v.z))), h2u(__hadd2(B23, u2h(u7v.w))));
            lsN[o+1]  = n + n7;
        }
        __syncthreads();                     // lsAB(hh) ready; eab free

        // ---- Stage C(hh)  ||  Stage A-store(hh+1) + prefetch(hh+2) ----
        if (tid < PQ) {
            __half2 A01 = hz, A23 = hz, B01 = hz, B23 = hz;
            unsigned n = 0u;
            #pragma unroll
            for (int j7 = 0; j7 < 7; ++j7) {
                int q = (pw + j7) * DLN + lidx;
                uint4 u = lsAB[q];
                A01 = __hadd2(A01, u2h(u.x)); A23 = __hadd2(A23, u2h(u.y));
                B01 = __hadd2(B01, u2h(u.z)); B23 = __hadd2(B23, u2h(u.w));
                n += lsN[q];
            }
            float2 fa01 = __half22float2(A01), fa23 = __half22float2(A23);
            float2 fb01 = __half22float2(B01), fb23 = __half22float2(B23);

            aA.x += fa01.x; aA.y += fa01.y; aA.z += fa23.x; aA.w += fa23.y;
            aB.x += fb01.x; aB.y += fb01.y; aB.z += fb23.x; aB.w += fb23.y;
            s02 += n & 0x00FF00FFu;
            s13 += (n >> 8) & 0x00FF00FFu;

            int rp = (hh % 7) * PQ + tid;
            if (hh >= 7) {
                uint4 oldv = rAB[rp];
                unsigned on = rN[rp];
                float2 c01 = __half22float2(u2h(oldv.x)), c23 = __half22float2(u2h(oldv.y));
                float2 d01 = __half22float2(u2h(oldv.z)), d23 = __half22float2(u2h(oldv.w));
                aA.x -= c01.x; aA.y -= c01.y; aA.z -= c23.x; aA.w -= c23.y;
                aB.x -= d01.x; aB.y -= d01.y; aB.z -= d23.x; aB.w -= d23.y;
                s02 -= on & 0x00FF00FFu;
                s13 -= (on >> 8) & 0x00FF00FFu;
            }
            rAB[rp] = make_uint4(h2u(A01), h2u(A23), h2u(B01), h2u(B23));
            rN[rp] = n;

            if (hh >= 6) {
                float N0 = (float)(s02 & 0xFFFFu);
                float N2 = (float)(s02 >> 16);
                float N1 = (float)(s13 & 0xFFFFu);
                float N3 = (float)(s13 >> 16);
                float n0, d0c, n1, d1, n2, d2, n3, d3;
                nd_class(aA.x, aB.x, N0, n0, d0c);
                nd_class(aA.y, aB.y, N1, n1, d1);
                nd_class(aA.z, aB.z, N2, n2, d2);
                nd_class(aA.w, aB.w, N3, n3, d3);
                float p01 = d0c * d1, p23 = d2 * d3;
                float num = fmaf(n0, d1, n1 * d0c) * p23 + fmaf(n2, d3, n3 * d2) * p01;
                lsum += __fdividef(num, p01 * p23);
            }
        }

        // A-store(hh+1) from prefetched regs; then issue prefetch(hh+2)
        if (hh + 1 < NITER) {
            stageA_store(eab, en, tid, pk0, pv0);
            if (hasA1) stageA_store(eab, en, tid + TPB, pk1, pv1);
            if (hh + 2 < NITER) {
                const int hN = h0 + hh + 2;
                const float* Xl = Xb + (size_t)hN * (WW * DD);
                const int*   Yl = Yb + (size_t)ys * (size_t)hN * (WW * DD);
                pk0 = Yl[off0 * ys]; pv0 = Xl[off0 + pk0 * CHST];
                if (hasA1) { pk1 = Yl[off1 * ys]; pv1 = Xl[off1 + pk1 * CHST]; }
            }
        }
    }
    __syncthreads();

    // ---- block reduce + global accumulate + last-block finalize ----
    float* red = (float*)sm;
    red[tid] = lsum;
    __syncthreads();
    if (tid < 128) red[tid] += red[tid + 128] + red[tid + 256];
    __syncthreads();
    if (tid < 64) red[tid] += red[tid + 64];
    __syncthreads();
    if (tid < 32) {
        float v = red[tid] + red[tid + 32];
        #pragma unroll
        for (int o = 16; o > 0; o >>= 1)
            v += __shfl_down_sync(0xffffffffu, v, o);
        if (tid == 0) {
            atomicAdd(&g_acc, (double)v);
            __threadfence();
            unsigned t = atomicAdd(&g_done, 1u);
            if (t == TOTB - 1) {
                double tot = g_acc;
                out[0] = (float)(1.0 - tot * (1.0 / 17075520.0));
                __threadfence();
                g_acc = 0.0;
                g_done = 0u;
            }
        }
    }
}

extern "C" void kernel_launch(void* const* d_in, const int* in_sizes, int n_in,
                              void* d_out, int out_size)
{
    (void)out_size;
    const float* X;
    const int*   Y;
    if (n_in >= 2 && in_sizes[0] == Y_ELEMS) {
        Y = (const int*)d_in[0];
        X = (const float*)d_in[1];
    } else {
        X = (const float*)d_in[0];
        Y = (const int*)d_in[1];
    }

    static int smem_set = 0;
    if (!smem_set) {
        cudaFuncSetAttribute(kf, cudaFuncAttributeMaxDynamicSharedMemorySize, SMEMF);
        smem_set = 1;
    }

    kf<<<dim3(NWCH, NHSEG, BB * 2), TPB, SMEMF>>>(X, Y, (float*)d_out);
}

// round 16
// speedup vs baseline: 1.0774x; 1.0516x over previous
#include <cuda_runtime.h>
#include <cuda_fp16.h>

// Shapes
#define BB   2
#define HH   160
#define WW   160
#define DD   96
#define WOUT 154
#define CHST (160*160*96)          // x channel stride (elements)
#define Y_ELEMS (BB*HH*WW*DD)      // 4,915,200

// Fused tiling: blocks tile (w-chunk x h-seg x (b, d-half)); all exact
#define WOCF 7                     // w outputs per block (154 = 22*7)
#define WICF 13
#define SEGH 22                    // h outputs per block (154 = 7*22)
#define NHSEG 7
#define NWCH 22
#define TPB  384
#define TOTB (NWCH*NHSEG*BB*2)     // 616
#define PQ   315                   // positions per block = 7*45
#define DIN  52                    // input d per half
#define DLN  46                    // D-window line outputs per half
#define NITER (SEGH+6)             // 28
#define NA   (WICF*DIN)            // 676 stage-A items
#define NB   (WICF*23)             // 299 stage-B pairs

// smem byte offsets (total 69,588 B -> 3 CTAs/SM); ALL uint4 offsets 16-aligned
#define OFF_EAB  0                  // uint4[676]  {A01,A23,B01,B23}
#define OFF_EN   10816              // u32 [676]   pre-shifted class count
#define OFF_LSAB 13520              // uint4[13*46] D-window line sums   (13520/16=845)
#define OFF_LSN  23088              // u32 [13*46]
#define OFF_RAB  25488              // uint4[7*315] ring of W-window sums (25488/16=1593)
#define OFF_RN   60768              // u32 [7*315]
#define SMEMF    69600

__device__ double   g_acc;          // zero-init at load; reset by last block
__device__ unsigned g_done;

__device__ __forceinline__ __half2 u2h(unsigned u) { return *reinterpret_cast<__half2*>(&u); }
__device__ __forceinline__ unsigned h2u(__half2 h) { return *reinterpret_cast<unsigned*>(&h); }

__device__ __forceinline__ void nd_class(float A, float B, float Nf,
                                         float& num, float& den)
{
    const float inv343 = 1.0f / 343.0f;
    const float K2C = 49.0f / 48.0f;
    const float K4C = K2C * K2C;
    const float Cc  = 0.00045f;            // (0.03*1)^2/2
    float yb  = Nf * inv343;
    float g1  = 1.0f - yb;
    float Ab  = A * inv343;
    float Bb  = B * inv343;
    num = fmaf(K2C * Ab, g1, Cc);
    float var = fmaf(-Ab, Ab, Bb);
    den = fmaf((K4C * var) * yb, g1, Cc);
}

// stage-A: convert one prefetched voxel and store expanded AoS entry
__device__ __forceinline__ void stageA_store(uint4* eab, unsigned* en,
                                             int idx, int k, float xv)
{
    float th;
    asm("tanh.approx.f32 %0, %1;" : "=f"(th) : "f"(0.5f * xv));
    float a = 0.5f * th;                   // sigmoid(x) - 0.5
    unsigned ha = (unsigned)__half_as_ushort(__float2half_rn(a));
    unsigned hb = (unsigned)__half_as_ushort(__float2half_rn(a * a));
    int sh = (k & 1) ? 16 : 0;
    unsigned sa = ha << sh, sbv = hb << sh;
    bool hi = (k & 2) != 0;
    eab[idx] = make_uint4(hi ? 0u : sa,  hi ? sa  : 0u,
                          hi ? 0u : sbv, hi ? sbv : 0u);
    en[idx] = 1u << (k * 8);
}

__global__ __launch_bounds__(TPB, 3) void kf(const float* __restrict__ X,
                                             const int* __restrict__ Y,
                                             float* __restrict__ out)
{
    extern __shared__ char sm[];
    uint4*    eab  = (uint4*)(sm + OFF_EAB);
    unsigned* en   = (unsigned*)(sm + OFF_EN);
    uint4*    lsAB = (uint4*)(sm + OFF_LSAB);
    unsigned* lsN  = (unsigned*)(sm + OFF_LSN);
    uint4*    rAB  = (uint4*)(sm + OFF_RAB);
    unsigned* rN   = (unsigned*)(sm + OFF_RN);

    const int tid = threadIdx.x;
    const int wb  = blockIdx.x * WOCF;
    const int h0  = blockIdx.y * SEGH;
    const int b   = blockIdx.z >> 1;
    const int gHalf = blockIdx.z & 1;      // d-half: 0 -> outputs 0..44, 1 -> 45..89
    const int d0  = gHalf * 44;            // input d base (52 inputs)

    // ---- y dtype probe (int64 -> odd 32-bit words all zero) ----
    __shared__ int s_ys;
    if (tid == 0) s_ys = 2;
    __syncthreads();
    if (tid < 128) { if (Y[2 * tid + 1] != 0) s_ys = 1; }
    __syncthreads();
    const int ys = s_ys;

    const float* Xb = X + (size_t)b * 4 * CHST;
    const int*   Yb = Y + (size_t)ys * (size_t)b * (HH * WW * DD);

    // stage-A ownership (items tid and tid+TPB)
    int off0, off1 = 0;
    const bool hasA1 = (tid + TPB < NA);   // tid < 292
    { int wl = tid / DIN, dl = tid - wl * DIN; off0 = (wb + wl) * 96 + d0 + dl; }
    if (hasA1) { int i1 = tid + TPB; int wl = i1 / DIN, dl = i1 - wl * DIN; off1 = (wb + wl) * 96 + d0 + dl; }

    // stage-C ownership: sliding-H accumulators, one position per thread
    float4 aA = make_float4(0.f, 0.f, 0.f, 0.f);
    float4 aB = aA;
    unsigned s02 = 0u, s13 = 0u;
    float lsum = 0.f;
    const int pw = (tid < PQ) ? (tid / 45) : 0;
    const int pd = (tid < PQ) ? (tid - pw * 45) : 0;
    const int lidx = pd + gHalf;

    // ---- prologue: prefetch row 0 (y then x[y] only) ----
    int   pk0 = 0, pk1 = 0;
    float pv0 = 0.f, pv1 = 0.f;
    {
        const float* Xl = Xb + (size_t)h0 * (WW * DD);
        const int*   Yl = Yb + (size_t)ys * (size_t)h0 * (WW * DD);
        pk0 = Yl[off0 * ys]; pv0 = Xl[off0 + pk0 * CHST];
        if (hasA1) { pk1 = Yl[off1 * ys]; pv1 = Xl[off1 + pk1 * CHST]; }
    }

    const __half2 hz = u2h(0u);

    for (int hh = 0; hh < NITER; ++hh) {
        // ---- Stage A: store prefetched row; issue prefetch for next row ----
        stageA_store(eab, en, tid, pk0, pv0);
        if (hasA1) stageA_store(eab, en, tid + TPB, pk1, pv1);
        if (hh + 1 < NITER) {
            const int hN = h0 + hh + 1;
            const float* Xl = Xb + (size_t)hN * (WW * DD);
            const int*   Yl = Yb + (size_t)ys * (size_t)hN * (WW * DD);
            pk0 = Yl[off0 * ys]; pv0 = Xl[off0 + pk0 * CHST];
            if (hasA1) { pk1 = Yl[off1 * ys]; pv1 = Xl[off1 + pk1 * CHST]; }
        }
        __syncthreads();                     // eab(hh) ready

        // ---- Stage B: D-window-7, paired (2 outputs share 6-tap core) ----
        if (tid < NB) {
            int wl = tid / 23;
            int de = (tid - wl * 23) * 2;
            int base = wl * DIN + de;
            __half2 A01 = hz, A23 = hz, B01 = hz, B23 = hz;
            unsigned n = 0u;
            #pragma unroll
            for (int t7 = 1; t7 < 7; ++t7) {
                uint4 u = eab[base + t7];
                A01 = __hadd2(A01, u2h(u.x)); A23 = __hadd2(A23, u2h(u.y));
                B01 = __hadd2(B01, u2h(u.z)); B23 = __hadd2(B23, u2h(u.w));
                n += en[base + t7];
            }
            uint4 u0v = eab[base];
            uint4 u7v = eab[base + 7];
            unsigned n0 = en[base], n7 = en[base + 7];
            int o = wl * DLN + de;
            lsAB[o]   = make_uint4(h2u(__hadd2(A01, u2h(u0v.x))), h2u(__hadd2(A23, u2h(u0v.y))),
                                   h2u(__hadd2(B01, u2h(u0v.z))), h2u(__hadd2(B23, u2h(u0v.w))));
            lsN[o]    = n + n0;
            lsAB[o+1] = make_uint4(h2u(__hadd2(A01, u2h(u7v.x))), h2u(__hadd2(A23, u2h(u7v.y))),
                                   h2u(__hadd2(B01, u2h(u7v.z))), h2u(__hadd2(B23, u2h(u7v.w))));
            lsN[o+1]  = n + n7;
        }
        __syncthreads();                     // lsAB(hh) ready; eab free

        // ---- Stage C: W-window-7 + sliding-H update + finalize ----
        if (tid < PQ) {
            __half2 A01 = hz, A23 = hz, B01 = hz, B23 = hz;
            unsigned n = 0u;
            #pragma unroll
            for (int j7 = 0; j7 < 7; ++j7) {
                int q = (pw + j7) * DLN + lidx;
                uint4 u = lsAB[q];
                A01 = __hadd2(A01, u2h(u.x)); A23 = __hadd2(A23, u2h(u.y));
                B01 = __hadd2(B01, u2h(u.z)); B23 = __hadd2(B23, u2h(u.w));
                n += lsN[q];
            }
            float2 fa01 = __half22float2(A01), fa23 = __half22float2(A23);
            float2 fb01 = __half22float2(B01), fb23 = __half22float2(B23);

            aA.x += fa01.x; aA.y += fa01.y; aA.z += fa23.x; aA.w += fa23.y;
            aB.x += fb01.x; aB.y += fb01.y; aB.z += fb23.x; aB.w += fb23.y;
            s02 += n & 0x00FF00FFu;
            s13 += (n >> 8) & 0x00FF00FFu;

            int rp = (hh % 7) * PQ + tid;
            if (hh >= 7) {
                uint4 oldv = rAB[rp];
                unsigned on = rN[rp];
                float2 c01 = __half22float2(u2h(oldv.x)), c23 = __half22float2(u2h(oldv.y));
                float2 d01 = __half22float2(u2h(oldv.z)), d23 = __half22float2(u2h(oldv.w));
                aA.x -= c01.x; aA.y -= c01.y; aA.z -= c23.x; aA.w -= c23.y;
                aB.x -= d01.x; aB.y -= d01.y; aB.z -= d23.x; aB.w -= d23.y;
                s02 -= on & 0x00FF00FFu;
                s13 -= (on >> 8) & 0x00FF00FFu;
            }
            rAB[rp] = make_uint4(h2u(A01), h2u(A23), h2u(B01), h2u(B23));
            rN[rp] = n;

            if (hh >= 6) {
                float N0 = (float)(s02 & 0xFFFFu);
                float N2 = (float)(s02 >> 16);
                float N1 = (float)(s13 & 0xFFFFu);
                float N3 = (float)(s13 >> 16);
                float n0, d0c, n1, d1, n2, d2, n3, d3;
                nd_class(aA.x, aB.x, N0, n0, d0c);
                nd_class(aA.y, aB.y, N1, n1, d1);
                nd_class(aA.z, aB.z, N2, n2, d2);
                nd_class(aA.w, aB.w, N3, n3, d3);
                float p01 = d0c * d1, p23 = d2 * d3;
                float num = fmaf(n0, d1, n1 * d0c) * p23 + fmaf(n2, d3, n3 * d2) * p01;
                lsum += __fdividef(num, p01 * p23);
            }
        }
        __syncthreads();
    }

    // ---- block reduce + global accumulate + last-block finalize ----
    float* red = (float*)sm;
    red[tid] = lsum;
    __syncthreads();
    if (tid < 128) red[tid] += red[tid + 128] + red[tid + 256];
    __syncthreads();
    if (tid < 64) red[tid] += red[tid + 64];
    __syncthreads();
    if (tid < 32) {
        float v = red[tid] + red[tid + 32];
        #pragma unroll
        for (int o = 16; o > 0; o >>= 1)
            v += __shfl_down_sync(0xffffffffu, v, o);
        if (tid == 0) {
            atomicAdd(&g_acc, (double)v);
            __threadfence();
            unsigned t = atomicAdd(&g_done, 1u);
            if (t == TOTB - 1) {
                double tot = g_acc;
                out[0] = (float)(1.0 - tot * (1.0 / 17075520.0));
                __threadfence();
                g_acc = 0.0;
                g_done = 0u;
            }
        }
    }
}

extern "C" void kernel_launch(void* const* d_in, const int* in_sizes, int n_in,
                              void* d_out, int out_size)
{
    (void)out_size;
    const float* X;
    const int*   Y;
    if (n_in >= 2 && in_sizes[0] == Y_ELEMS) {
        Y = (const int*)d_in[0];
        X = (const float*)d_in[1];
    } else {
        X = (const float*)d_in[0];
        Y = (const int*)d_in[1];
    }

    static int smem_set = 0;
    if (!smem_set) {
        cudaFuncSetAttribute(kf, cudaFuncAttributeMaxDynamicSharedMemorySize, SMEMF);
        smem_set = 1;
    }

    kf<<<dim3(NWCH, NHSEG, BB * 2), TPB, SMEMF>>>(X, Y, (float*)d_out);
}

// round 17
// speedup vs baseline: 1.1477x; 1.0652x over previous
#include <cuda_runtime.h>
#include <cuda_fp16.h>

// Shapes
#define BB   2
#define HH   160
#define WW   160
#define DD   96
#define WOUT 154
#define CHST (160*160*96)          // x channel stride (elements)
#define Y_ELEMS (BB*HH*WW*DD)      // 4,915,200

// Fused tiling: blocks tile (w-chunk x h-seg x (b, d-half))
#define WOCF 8                     // w outputs per block (last chunk: 2)
#define SEGH 22                    // h outputs per block (154 = 7*22)
#define NHSEG 7
#define NWCH 20
#define TPB  384
#define TOTB (NWCH*NHSEG*BB*2)     // 560
#define PMAX (WOCF*45)             // 360 positions per block
#define DIN  52                    // input d per half
#define DLN  46                    // D-window line outputs per half
#define NITER (SEGH+6)             // 28

// smem byte offsets (total 75,664 B -> 3 CTAs/SM); all uint4 offsets 16-aligned
#define OFF_EABE 0                  // uint4[14*26=364] even-d expanded entries
#define OFF_EABO 5824               // uint4[364]       odd-d expanded entries
#define OFF_EN   11648              // u8  [14*52=728]  class id
#define OFF_LSAB 12384              // uint4[14*46=644] D-window line sums
#define OFF_LSN  22688              // u32 [644]
#define OFF_RAB  25264              // uint4[7*360=2520] ring of W-window sums
#define OFF_RN   65584              // u32 [2520]
#define SMEMF    75664

__device__ double   g_acc;          // zero-init at load; reset by last block
__device__ unsigned g_done;

__device__ __forceinline__ __half2 u2h(unsigned u) { return *reinterpret_cast<__half2*>(&u); }
__device__ __forceinline__ unsigned h2u(__half2 h) { return *reinterpret_cast<unsigned*>(&h); }

__device__ __forceinline__ void nd_class(float A, float B, float Nf,
                                         float& num, float& den)
{
    const float inv343 = 1.0f / 343.0f;
    const float K2C = 49.0f / 48.0f;
    const float K4C = K2C * K2C;
    const float Cc  = 0.00045f;            // (0.03*1)^2/2
    float yb  = Nf * inv343;
    float g1  = 1.0f - yb;
    float Ab  = A * inv343;
    float Bb  = B * inv343;
    num = fmaf(K2C * Ab, g1, Cc);
    float var = fmaf(-Ab, Ab, Bb);
    den = fmaf((K4C * var) * yb, g1, Cc);
}

// convert one voxel -> expanded uint4 {A01,A23,B01,B23}
__device__ __forceinline__ uint4 expand_entry(int k, float xv)
{
    float th;
    asm("tanh.approx.f32 %0, %1;" : "=f"(th) : "f"(0.5f * xv));
    float a = 0.5f * th;                   // sigmoid(x) - 0.5
    unsigned ha = (unsigned)__half_as_ushort(__float2half_rn(a));
    unsigned hb = (unsigned)__half_as_ushort(__float2half_rn(a * a));
    int sh = (k & 1) ? 16 : 0;
    unsigned sa = ha << sh, sbv = hb << sh;
    bool hi = (k & 2) != 0;
    return make_uint4(hi ? 0u : sa,  hi ? sa  : 0u,
                      hi ? 0u : sbv, hi ? sbv : 0u);
}

__device__ __forceinline__ void acc4(uint4& s, const uint4 v)
{
    s.x = h2u(__hadd2(u2h(s.x), u2h(v.x)));
    s.y = h2u(__hadd2(u2h(s.y), u2h(v.y)));
    s.z = h2u(__hadd2(u2h(s.z), u2h(v.z)));
    s.w = h2u(__hadd2(u2h(s.w), u2h(v.w)));
}

__global__ __launch_bounds__(TPB, 3) void kf(const float* __restrict__ X,
                                             const int* __restrict__ Y,
                                             float* __restrict__ out)
{
    extern __shared__ char sm[];
    uint4*         eabE = (uint4*)(sm + OFF_EABE);
    uint4*         eabO = (uint4*)(sm + OFF_EABO);
    unsigned char* en   = (unsigned char*)(sm + OFF_EN);
    uint4*         lsAB = (uint4*)(sm + OFF_LSAB);
    unsigned*      lsN  = (unsigned*)(sm + OFF_LSN);
    uint4*         rAB  = (uint4*)(sm + OFF_RAB);
    unsigned*      rN   = (unsigned*)(sm + OFF_RN);

    const int tid = threadIdx.x;
    const int wb  = blockIdx.x * WOCF;
    const int woc = min(WOCF, WOUT - wb);  // last chunk: 2
    const int wic = woc + 6;
    const int h0  = blockIdx.y * SEGH;
    const int b   = blockIdx.z >> 1;
    const int gHalf = blockIdx.z & 1;      // d-half: 0 -> outputs 0..44, 1 -> 45..89
    const int d0  = gHalf * 44;            // input d base (52 inputs)
    const int P   = woc * 45;

    // ---- y dtype probe (int64 -> odd 32-bit words all zero) ----
    __shared__ int s_ys;
    if (tid == 0) s_ys = 2;
    __syncthreads();
    if (tid < 128) { if (Y[2 * tid + 1] != 0) s_ys = 1; }
    __syncthreads();
    const int ys = s_ys;

    const float* Xb = X + (size_t)b * 4 * CHST;
    const int*   Yb = Y + (size_t)ys * (size_t)b * (HH * WW * DD);

    const int nA = wic * DIN;
    const int nB = wic * 23;

    // stage-A ownership (items tid and tid+TPB), hoisted indices
    int off0 = 0, off1 = 0, eI0 = 0, eI1 = 0, par0 = 0, par1 = 0;
    const bool hasA0 = (tid < nA);
    const bool hasA1 = (tid + TPB < nA);
    if (hasA0) {
        int wl = tid / DIN, dl = tid - wl * DIN;
        off0 = (wb + wl) * 96 + d0 + dl;
        eI0 = wl * 26 + (dl >> 1); par0 = dl & 1;
    }
    if (hasA1) {
        int i1 = tid + TPB;
        int wl = i1 / DIN, dl = i1 - wl * DIN;
        off1 = (wb + wl) * 96 + d0 + dl;
        eI1 = wl * 26 + (dl >> 1); par1 = dl & 1;
    }

    // stage-C ownership: sliding-H accumulators, one position per thread
    float4 aA = make_float4(0.f, 0.f, 0.f, 0.f);
    float4 aB = aA;
    unsigned s02 = 0u, s13 = 0u;
    float lsum = 0.f;
    const int pw = (tid < P) ? (tid / 45) : 0;
    const int pd = (tid < P) ? (tid - pw * 45) : 0;
    const int lidx = pd + gHalf;

    // ---- prefetch row 0: y then x[y] only ----
    int   pk0 = 0, pk1 = 0;
    float pv0 = 0.f, pv1 = 0.f;
    {
        const float* Xl = Xb + (size_t)h0 * (WW * DD);
        const int*   Yl = Yb + (size_t)ys * (size_t)h0 * (WW * DD);
        if (hasA0) { pk0 = Yl[off0 * ys]; pv0 = Xl[off0 + pk0 * CHST]; }
        if (hasA1) { pk1 = Yl[off1 * ys]; pv1 = Xl[off1 + pk1 * CHST]; }
    }

    const __half2 hz = u2h(0u);

    for (int hh = 0; hh < NITER; ++hh) {
        // ---- Stage A: store prefetched row (parity-split); prefetch next ----
        if (hasA0) {
            uint4 v = expand_entry(pk0, pv0);
            if (par0) eabO[eI0] = v; else eabE[eI0] = v;
            en[tid] = (unsigned char)pk0;
        }
        if (hasA1) {
            uint4 v = expand_entry(pk1, pv1);
            if (par1) eabO[eI1] = v; else eabE[eI1] = v;
            en[tid + TPB] = (unsigned char)pk1;
        }
        if (hh + 1 < NITER) {
            const int hN = h0 + hh + 1;
            const float* Xl = Xb + (size_t)hN * (WW * DD);
            const int*   Yl = Yb + (size_t)ys * (size_t)hN * (WW * DD);
            if (hasA0) { pk0 = Yl[off0 * ys]; pv0 = Xl[off0 + pk0 * CHST]; }
            if (hasA1) { pk1 = Yl[off1 * ys]; pv1 = Xl[off1 + pk1 * CHST]; }
        }
        __syncthreads();                     // eab(hh) ready

        // ---- Stage B: D-window-7, paired; parity-split conflict-free reads ----
        if (tid < nB) {
            int wl = tid / 23;
            int dp = tid - wl * 23;          // de = 2*dp
            int eb = wl * 26 + dp;
            int nbase = wl * DIN + 2 * dp;
            // taps (relative d): even -> E[dp + t/2], odd -> O[dp + (t-1)/2]
            uint4 e0v = eabE[eb],     e1v = eabE[eb + 1];
            uint4 e2v = eabE[eb + 2], e3v = eabE[eb + 3];
            uint4 o0v = eabO[eb],     o1v = eabO[eb + 1];
            uint4 o2v = eabO[eb + 2], o3v = eabO[eb + 3];
            // core = taps 1..6 = o0,e1,o1,e2,o2,e3
            uint4 core = o0v;
            acc4(core, e1v); acc4(core, o1v); acc4(core, e2v);
            acc4(core, o2v); acc4(core, e3v);
            unsigned n = 0u;
            #pragma unroll
            for (int t7 = 1; t7 < 7; ++t7) n += 1u << (en[nbase + t7] * 8);
            unsigned n0 = 1u << (en[nbase] * 8);
            unsigned n7 = 1u << (en[nbase + 7] * 8);

            uint4 out0 = core; acc4(out0, e0v);   // tap 0
            uint4 out1 = core; acc4(out1, o3v);   // tap 7
            int o = wl * DLN + 2 * dp;
            lsAB[o]     = out0;  lsN[o]     = n + n0;
            lsAB[o + 1] = out1;  lsN[o + 1] = n + n7;
        }
        __syncthreads();                     // lsAB(hh) ready; eab free

        // ---- Stage C: W-window-7 + sliding-H update + finalize ----
        if (tid < P) {
            __half2 A01 = hz, A23 = hz, B01 = hz, B23 = hz;
            unsigned n = 0u;
            #pragma unroll
            for (int j7 = 0; j7 < 7; ++j7) {
                int q = (pw + j7) * DLN + lidx;
                uint4 u = lsAB[q];
                A01 = __hadd2(A01, u2h(u.x)); A23 = __hadd2(A23, u2h(u.y));
                B01 = __hadd2(B01, u2h(u.z)); B23 = __hadd2(B23, u2h(u.w));
                n += lsN[q];
            }
            float2 fa01 = __half22float2(A01), fa23 = __half22float2(A23);
            float2 fb01 = __half22float2(B01), fb23 = __half22float2(B23);

            aA.x += fa01.x; aA.y += fa01.y; aA.z += fa23.x; aA.w += fa23.y;
            aB.x += fb01.x; aB.y += fb01.y; aB.z += fb23.x; aB.w += fb23.y;
            s02 += n & 0x00FF00FFu;
            s13 += (n >> 8) & 0x00FF00FFu;

            int rp = (hh % 7) * PMAX + tid;
            if (hh >= 7) {
                uint4 oldv = rAB[rp];
                unsigned on = rN[rp];
                float2 c01 = __half22float2(u2h(oldv.x)), c23 = __half22float2(u2h(oldv.y));
                float2 d01 = __half22float2(u2h(oldv.z)), d23 = __half22float2(u2h(oldv.w));
                aA.x -= c01.x; aA.y -= c01.y; aA.z -= c23.x; aA.w -= c23.y;
                aB.x -= d01.x; aB.y -= d01.y; aB.z -= d23.x; aB.w -= d23.y;
                s02 -= on & 0x00FF00FFu;
                s13 -= (on >> 8) & 0x00FF00FFu;
            }
            rAB[rp] = make_uint4(h2u(A01), h2u(A23), h2u(B01), h2u(B23));
            rN[rp] = n;

            if (hh >= 6) {
                float N0 = (float)(s02 & 0xFFFFu);
                float N2 = (float)(s02 >> 16);
                float N1 = (float)(s13 & 0xFFFFu);
                float N3 = (float)(s13 >> 16);
                float n0, d0c, n1, d1, n2, d2, n3, d3;
                nd_class(aA.x, aB.x, N0, n0, d0c);
                nd_class(aA.y, aB.y, N1, n1, d1);
                nd_class(aA.z, aB.z, N2, n2, d2);
                nd_class(aA.w, aB.w, N3, n3, d3);
                float p01 = d0c * d1, p23 = d2 * d3;
                float num = fmaf(n0, d1, n1 * d0c) * p23 + fmaf(n2, d3, n3 * d2) * p01;
                lsum += __fdividef(num, p01 * p23);
            }
        }
        __syncthreads();
    }

    // ---- block reduce + global accumulate + last-block finalize ----
    float* red = (float*)sm;
    red[tid] = lsum;
    __syncthreads();
    if (tid < 128) red[tid] += red[tid + 128] + red[tid + 256];
    __syncthreads();
    if (tid < 64) red[tid] += red[tid + 64];
    __syncthreads();
    if (tid < 32) {
        float v = red[tid] + red[tid + 32];
        #pragma unroll
        for (int o = 16; o > 0; o >>= 1)
            v += __shfl_down_sync(0xffffffffu, v, o);
        if (tid == 0) {
            atomicAdd(&g_acc, (double)v);
            __threadfence();
            unsigned t = atomicAdd(&g_done, 1u);
            if (t == TOTB - 1) {
                double tot = g_acc;
                out[0] = (float)(1.0 - tot * (1.0 / 17075520.0));
                __threadfence();
                g_acc = 0.0;
                g_done = 0u;
            }
        }
    }
}

extern "C" void kernel_launch(void* const* d_in, const int* in_sizes, int n_in,
                              void* d_out, int out_size)
{
    (void)out_size;
    const float* X;
    const int*   Y;
    if (n_in >= 2 && in_sizes[0] == Y_ELEMS) {
        Y = (const int*)d_in[0];
        X = (const float*)d_in[1];
    } else {
        X = (const float*)d_in[0];
        Y = (const int*)d_in[1];
    }

    static int smem_set = 0;
    if (!smem_set) {
        cudaFuncSetAttribute(kf, cudaFuncAttributeMaxDynamicSharedMemorySize, SMEMF);
        smem_set = 1;
    }

    kf<<<dim3(NWCH, NHSEG, BB * 2), TPB, SMEMF>>>(X, Y, (float*)d_out);
}